// round 6
// baseline (speedup 1.0000x reference)
#include <cuda_runtime.h>
#include <cuda_bf16.h>

// out[n,:] = trace-contraction of the Jacobian of the antisymmetric field
// A(p)=M-M^T (M upper-tri from v=MLP(p), 3->32->32->32->3, softplus beta=20):
//   out0 =  Jv[0][1] + Jv[1][2]
//   out1 = -Jv[0][0] + Jv[2][2]
//   out2 = -Jv[1][0] - Jv[2][1],   Jv[c][j] = dv_c/dx_j
// Forward pass (sigmoid(20z) diagonals) + 3 simultaneous forward-mode tangents.
//
// DECOMPOSITION (anti-spill): one WARP per sample, one LANE per neuron.
// Per-thread state is pure scalars (~40 regs): d1,d2,d3, 3 tangent accums,
// 9 cached per-neuron weights. Activation/tangent vectors are exchanged via a
// 256-float per-warp smem buffer. No per-thread vectors exist -> no stack frame.

#define BETAF 20.0f
#define INV_BETAF 0.05f
#define BLOCK 256
#define WPB (BLOCK / 32)
#define GRID 2432  // 152 SMs * 16

__device__ __forceinline__ float act_d(float z) {           // sigmoid(20z)
    float y = BETAF * z;
    float e = __expf(-fabsf(y));
    float r = __fdividef(1.0f, 1.0f + e);
    return (y >= 0.0f) ? r : e * r;
}
__device__ __forceinline__ float act_h(float z) {           // softplus(20z)/20
    float y = BETAF * z;
    float e = __expf(-fabsf(y));
    return fmaxf(z, 0.0f) + __logf(1.0f + e) * INV_BETAF;
}

// forward matvec step: acc += h4-broadcast * W[(4kk+c)*32+lane]
#define FWD_STEP(W, HB, kk)                                                    \
    {                                                                          \
        const float4 h4 = *reinterpret_cast<const float4*>(&(HB)[(kk) * 4]);   \
        acc = fmaf(h4.x, (W)[((kk) * 4 + 0) * 32 + lane], acc);                \
        acc = fmaf(h4.y, (W)[((kk) * 4 + 1) * 32 + lane], acc);                \
        acc = fmaf(h4.z, (W)[((kk) * 4 + 2) * 32 + lane], acc);                \
        acc = fmaf(h4.w, (W)[((kk) * 4 + 3) * 32 + lane], acc);                \
    }

// triple-tangent matvec step: one W element feeds 3 FMAs
#define TRI_STEP(W, TB, kk)                                                    \
    {                                                                          \
        const float4 t0 = *reinterpret_cast<const float4*>(&(TB)[(kk) * 4]);        \
        const float4 t1 = *reinterpret_cast<const float4*>(&(TB)[32 + (kk) * 4]);   \
        const float4 t2 = *reinterpret_cast<const float4*>(&(TB)[64 + (kk) * 4]);   \
        float w;                                                               \
        w = (W)[((kk) * 4 + 0) * 32 + lane];                                   \
        a0 = fmaf(t0.x, w, a0); a1 = fmaf(t1.x, w, a1); a2 = fmaf(t2.x, w, a2);\
        w = (W)[((kk) * 4 + 1) * 32 + lane];                                   \
        a0 = fmaf(t0.y, w, a0); a1 = fmaf(t1.y, w, a1); a2 = fmaf(t2.y, w, a2);\
        w = (W)[((kk) * 4 + 2) * 32 + lane];                                   \
        a0 = fmaf(t0.z, w, a0); a1 = fmaf(t1.z, w, a1); a2 = fmaf(t2.z, w, a2);\
        w = (W)[((kk) * 4 + 3) * 32 + lane];                                   \
        a0 = fmaf(t0.w, w, a0); a1 = fmaf(t1.w, w, a1); a2 = fmaf(t2.w, w, a2);\
    }

__global__ __launch_bounds__(BLOCK, 2) void NCL_50766513438744_kernel(
    const float* __restrict__ x,
    const float* __restrict__ W1, const float* __restrict__ b1,
    const float* __restrict__ W2, const float* __restrict__ b2,
    const float* __restrict__ W3, const float* __restrict__ b3,
    const float* __restrict__ W4,
    float* __restrict__ out, int N, int totalWarps)
{
    __shared__ __align__(16) float sW2[1024];          // [k][m] row-major
    __shared__ __align__(16) float sW3[1024];
    __shared__ __align__(16) float sBuf[WPB * 256];    // per-warp h/t buffers

    for (int idx = threadIdx.x; idx < 1024; idx += BLOCK) {
        sW2[idx] = W2[idx];
        sW3[idx] = W3[idx];
    }
    __syncthreads();

    const int lane = threadIdx.x & 31;
    const int wib  = threadIdx.x >> 5;
    float* const hb1 = &sBuf[wib * 256];      // h1  [32]
    float* const hb2 = hb1 + 32;              // h2  [32]
    float* const tb1 = hb1 + 64;              // t1  [3][32]
    float* const tb2 = hb1 + 160;             // t2  [3][32]

    // per-neuron constants (lane = neuron index m)
    const float w1_0 = W1[lane], w1_1 = W1[32 + lane], w1_2 = W1[64 + lane];
    const float b1r = b1[lane], b2r = b2[lane], b3r = b3[lane];
    const float w4_0 = W4[lane * 3 + 0], w4_1 = W4[lane * 3 + 1], w4_2 = W4[lane * 3 + 2];

    const int gw = blockIdx.x * WPB + wib;
    for (int s = gw; s < N; s += totalWarps) {
        const float x0 = __ldg(x + 3 * s + 0);
        const float x1 = __ldg(x + 3 * s + 1);
        const float x2 = __ldg(x + 3 * s + 2);

        // ---- layer 1 ----
        float acc = fmaf(x0, w1_0, fmaf(x1, w1_1, fmaf(x2, w1_2, b1r)));
        const float d1v = act_d(acc);
        hb1[lane] = act_h(acc);
        __syncwarp();

        // ---- layer 2 forward ----
        acc = b2r;
        #pragma unroll
        for (int kk = 0; kk < 8; ++kk) FWD_STEP(sW2, hb1, kk)
        const float d2v = act_d(acc);
        hb2[lane] = act_h(acc);
        __syncwarp();

        // ---- layer 3 forward (derivative only) ----
        acc = b3r;
        #pragma unroll
        for (int kk = 0; kk < 8; ++kk) FWD_STEP(sW3, hb2, kk)
        const float d3v = act_d(acc);

        // ---- tangent seed: t1_j = d1 * W1[j][m] ----
        tb1[lane]      = d1v * w1_0;
        tb1[32 + lane] = d1v * w1_1;
        tb1[64 + lane] = d1v * w1_2;
        __syncwarp();

        // ---- tangent layer 2 (3 tangents share each W2 element) ----
        float a0 = 0.0f, a1 = 0.0f, a2 = 0.0f;
        #pragma unroll
        for (int kk = 0; kk < 8; ++kk) TRI_STEP(sW2, tb1, kk)
        tb2[lane]      = d2v * a0;
        tb2[32 + lane] = d2v * a1;
        tb2[64 + lane] = d2v * a2;
        __syncwarp();

        // ---- tangent layer 3 ----
        a0 = 0.0f; a1 = 0.0f; a2 = 0.0f;
        #pragma unroll
        for (int kk = 0; kk < 8; ++kk) TRI_STEP(sW3, tb2, kk)
        const float s0 = d3v * a0;
        const float s1 = d3v * a1;
        const float s2 = d3v * a2;

        // ---- layer 4 + antisymmetric trace contraction (per-lane partials) ----
        float po0 = fmaf(s1, w4_0, s2 * w4_1);            //  Jv[0][1]+Jv[1][2]
        float po1 = fmaf(s2, w4_2, -(s0 * w4_0));         // -Jv[0][0]+Jv[2][2]
        float po2 = -fmaf(s0, w4_1, s1 * w4_2);           // -Jv[1][0]-Jv[2][1]

        // warp reduction
        #pragma unroll
        for (int off = 16; off; off >>= 1) {
            po0 += __shfl_xor_sync(0xffffffffu, po0, off);
            po1 += __shfl_xor_sync(0xffffffffu, po1, off);
            po2 += __shfl_xor_sync(0xffffffffu, po2, off);
        }
        if (lane == 0) {
            out[3 * s + 0] = po0;
            out[3 * s + 1] = po1;
            out[3 * s + 2] = po2;
        }
        // buffer reuse across iterations is protected by the syncwarps above
    }
}

extern "C" void kernel_launch(void* const* d_in, const int* in_sizes, int n_in,
                              void* d_out, int out_size) {
    const float* x  = (const float*)d_in[0];
    const float* W1 = (const float*)d_in[1];
    const float* b1 = (const float*)d_in[2];
    const float* W2 = (const float*)d_in[3];
    const float* b2 = (const float*)d_in[4];
    const float* W3 = (const float*)d_in[5];
    const float* b3 = (const float*)d_in[6];
    const float* W4 = (const float*)d_in[7];
    // d_in[8] = b4: not needed (bias drops out of the Jacobian)
    float* out = (float*)d_out;

    const int N = in_sizes[0] / 3;
    const int totalWarps = GRID * WPB;
    NCL_50766513438744_kernel<<<GRID, BLOCK>>>(x, W1, b1, W2, b2, W3, b3, W4,
                                               out, N, totalWarps);
}

// round 7
// speedup vs baseline: 1.4284x; 1.4284x over previous
#include <cuda_runtime.h>
#include <cuda_bf16.h>

// out[n,:] = trace-contraction of the Jacobian of the antisymmetric field
// A(p)=M-M^T (M upper-tri from v=MLP(p), 3->32->32->32->3, softplus beta=20):
//   out0 =  Jv[0][1] + Jv[1][2]
//   out1 = -Jv[0][0] + Jv[2][2]
//   out2 = -Jv[1][0] - Jv[2][1],   Jv[c][j] = dv_c/dx_j
// Forward pass (sigmoid(20z) diagonals) + 3 simultaneous forward-mode tangents.
//
// Decomposition: one WARP per sample, one LANE per neuron.
// R6 change vs R5 (which was 92.7% l1tex-bound): W2/W3 COLUMNS LIVE IN
// REGISTERS (64 named const scalars per lane) -> smem carries only broadcast
// float4 reads of the h/t vectors. Also: fused act (1x expf), 4-way split
// forward accumulator for FMA-latency cover.

#define BETAF 20.0f
#define INV_BETAF 0.05f
#define BLOCK 256
#define WPB (BLOCK / 32)
#define GRID 2432  // 152 SMs * 16 blocks

__device__ __forceinline__ void act_hd(float z, float& h, float& d) {
    float y = BETAF * z;
    float e = __expf(-fabsf(y));
    float r = __fdividef(1.0f, 1.0f + e);
    d = (y >= 0.0f) ? r : e * r;                       // sigmoid(20z)
    h = fmaxf(z, 0.0f) + __logf(1.0f + e) * INV_BETAF; // softplus(20z)/20
}
__device__ __forceinline__ float act_d(float z) {
    float y = BETAF * z;
    float e = __expf(-fabsf(y));
    float r = __fdividef(1.0f, 1.0f + e);
    return (y >= 0.0f) ? r : e * r;
}

// declare + load one W column entry: P##i = G[i*32 + lane]
#define LW(i, P, G) const float P##i = (G)[(i) * 32 + lane];
#define REP32(F, A, B) F(0,A,B)F(1,A,B)F(2,A,B)F(3,A,B)F(4,A,B)F(5,A,B)F(6,A,B)F(7,A,B) \
    F(8,A,B)F(9,A,B)F(10,A,B)F(11,A,B)F(12,A,B)F(13,A,B)F(14,A,B)F(15,A,B) \
    F(16,A,B)F(17,A,B)F(18,A,B)F(19,A,B)F(20,A,B)F(21,A,B)F(22,A,B)F(23,A,B) \
    F(24,A,B)F(25,A,B)F(26,A,B)F(27,A,B)F(28,A,B)F(29,A,B)F(30,A,B)F(31,A,B)

// forward matvec chunk: 4 broadcast h values x register W, 4 acc chains
#define FWD4(P, i0,i1,i2,i3, HB, base) { \
    const float4 h4 = *reinterpret_cast<const float4*>(&(HB)[base]); \
    accA = fmaf(h4.x, P##i0, accA); accB = fmaf(h4.y, P##i1, accB); \
    accC = fmaf(h4.z, P##i2, accC); accD = fmaf(h4.w, P##i3, accD); }
#define FWD_MATVEC(P, HB) \
    FWD4(P,0,1,2,3,HB,0)     FWD4(P,4,5,6,7,HB,4) \
    FWD4(P,8,9,10,11,HB,8)   FWD4(P,12,13,14,15,HB,12) \
    FWD4(P,16,17,18,19,HB,16)FWD4(P,20,21,22,23,HB,20) \
    FWD4(P,24,25,26,27,HB,24)FWD4(P,28,29,30,31,HB,28)

// triple-tangent matvec chunk: one W register feeds 3 tangent FMA chains
#define TRI1(P, k, c) \
    a0 = fmaf(t0.c, P##k, a0); a1 = fmaf(t1.c, P##k, a1); a2 = fmaf(t2.c, P##k, a2);
#define TRI4(P, k0,k1,k2,k3, TB, base) { \
    const float4 t0 = *reinterpret_cast<const float4*>(&(TB)[base]); \
    const float4 t1 = *reinterpret_cast<const float4*>(&(TB)[32 + (base)]); \
    const float4 t2 = *reinterpret_cast<const float4*>(&(TB)[64 + (base)]); \
    TRI1(P,k0,x) TRI1(P,k1,y) TRI1(P,k2,z) TRI1(P,k3,w) }
#define TRI_MATVEC(P, TB) \
    TRI4(P,0,1,2,3,TB,0)     TRI4(P,4,5,6,7,TB,4) \
    TRI4(P,8,9,10,11,TB,8)   TRI4(P,12,13,14,15,TB,12) \
    TRI4(P,16,17,18,19,TB,16)TRI4(P,20,21,22,23,TB,20) \
    TRI4(P,24,25,26,27,TB,24)TRI4(P,28,29,30,31,TB,28)

__global__ __launch_bounds__(BLOCK, 2) void NCL_50766513438744_kernel(
    const float* __restrict__ x,
    const float* __restrict__ W1, const float* __restrict__ b1,
    const float* __restrict__ W2, const float* __restrict__ b2,
    const float* __restrict__ W3, const float* __restrict__ b3,
    const float* __restrict__ W4,
    float* __restrict__ out, int N, int totalWarps)
{
    // per-warp exchange buffers: hb1[32] hb2[32] tb1[96] tb2[96] = 256 floats
    __shared__ __align__(16) float sBuf[WPB * 256];

    const int lane = threadIdx.x & 31;
    const int wib  = threadIdx.x >> 5;
    float* const hb1 = &sBuf[wib * 256];
    float* const hb2 = hb1 + 32;
    float* const tb1 = hb1 + 64;
    float* const tb2 = hb1 + 160;

    // W2/W3 column `lane` in registers (the R6 change): w2_0..w2_31, w3_0..w3_31
    REP32(LW, w2, W2)
    REP32(LW, w3, W3)

    // per-neuron constants
    const float w1_0 = W1[lane], w1_1 = W1[32 + lane], w1_2 = W1[64 + lane];
    const float b1r = b1[lane], b2r = b2[lane], b3r = b3[lane];
    const float w4_0 = W4[lane * 3 + 0], w4_1 = W4[lane * 3 + 1], w4_2 = W4[lane * 3 + 2];

    const int gw = blockIdx.x * WPB + wib;
    for (int s = gw; s < N; s += totalWarps) {
        const float x0 = __ldg(x + 3 * s + 0);
        const float x1 = __ldg(x + 3 * s + 1);
        const float x2 = __ldg(x + 3 * s + 2);

        // ---- layer 1 ----
        float h1v, d1v;
        act_hd(fmaf(x0, w1_0, fmaf(x1, w1_1, fmaf(x2, w1_2, b1r))), h1v, d1v);
        hb1[lane] = h1v;
        __syncwarp();

        // ---- layer 2 forward ----
        float h2v, d2v;
        {
            float accA = b2r, accB = 0.0f, accC = 0.0f, accD = 0.0f;
            FWD_MATVEC(w2, hb1)
            act_hd((accA + accB) + (accC + accD), h2v, d2v);
        }
        hb2[lane] = h2v;
        __syncwarp();

        // ---- layer 3 forward (derivative only) ----
        float d3v;
        {
            float accA = b3r, accB = 0.0f, accC = 0.0f, accD = 0.0f;
            FWD_MATVEC(w3, hb2)
            d3v = act_d((accA + accB) + (accC + accD));
        }

        // ---- tangent seed: t1_j = d1 * W1[j][m] ----
        tb1[lane]      = d1v * w1_0;
        tb1[32 + lane] = d1v * w1_1;
        tb1[64 + lane] = d1v * w1_2;
        __syncwarp();

        // ---- tangent layer 2 ----
        float s0, s1, s2;
        {
            float a0 = 0.0f, a1 = 0.0f, a2 = 0.0f;
            TRI_MATVEC(w2, tb1)
            tb2[lane]      = d2v * a0;
            tb2[32 + lane] = d2v * a1;
            tb2[64 + lane] = d2v * a2;
        }
        __syncwarp();

        // ---- tangent layer 3 ----
        {
            float a0 = 0.0f, a1 = 0.0f, a2 = 0.0f;
            TRI_MATVEC(w3, tb2)
            s0 = d3v * a0; s1 = d3v * a1; s2 = d3v * a2;
        }

        // ---- layer 4 + antisymmetric trace contraction (per-lane partials) ----
        float po0 = fmaf(s1, w4_0, s2 * w4_1);     //  Jv[0][1]+Jv[1][2]
        float po1 = fmaf(s2, w4_2, -(s0 * w4_0));  // -Jv[0][0]+Jv[2][2]
        float po2 = -fmaf(s0, w4_1, s1 * w4_2);    // -Jv[1][0]-Jv[2][1]

        #pragma unroll
        for (int off = 16; off; off >>= 1) {
            po0 += __shfl_xor_sync(0xffffffffu, po0, off);
            po1 += __shfl_xor_sync(0xffffffffu, po1, off);
            po2 += __shfl_xor_sync(0xffffffffu, po2, off);
        }
        if (lane == 0) {
            out[3 * s + 0] = po0;
            out[3 * s + 1] = po1;
            out[3 * s + 2] = po2;
        }
        // next-iteration buffer writes are ordered by the syncwarps above
    }
}

extern "C" void kernel_launch(void* const* d_in, const int* in_sizes, int n_in,
                              void* d_out, int out_size) {
    const float* x  = (const float*)d_in[0];
    const float* W1 = (const float*)d_in[1];
    const float* b1 = (const float*)d_in[2];
    const float* W2 = (const float*)d_in[3];
    const float* b2 = (const float*)d_in[4];
    const float* W3 = (const float*)d_in[5];
    const float* b3 = (const float*)d_in[6];
    const float* W4 = (const float*)d_in[7];
    // d_in[8] = b4: not needed (bias drops out of the Jacobian)
    float* out = (float*)d_out;

    const int N = in_sizes[0] / 3;
    const int totalWarps = GRID * WPB;
    NCL_50766513438744_kernel<<<GRID, BLOCK>>>(x, W1, b1, W2, b2, W3, b3, W4,
                                               out, N, totalWarps);
}

// round 8
// speedup vs baseline: 1.6835x; 1.1786x over previous
#include <cuda_runtime.h>
#include <cuda_bf16.h>

// out[n,:] = trace-contraction of the Jacobian of the antisymmetric field
// A(p)=M-M^T (M upper-tri from v=MLP(p), 3->32->32->32->3, softplus beta=20):
//   out0 =  Jv[0][1] + Jv[1][2]
//   out1 = -Jv[0][0] + Jv[2][2]
//   out2 = -Jv[1][0] - Jv[2][1],   Jv[c][j] = dv_c/dx_j
// Forward pass (sigmoid(20z) diagonals) + 3 simultaneous forward-mode tangents.
//
// Decomposition: one WARP per TWO samples, one LANE per neuron.
// R7 change vs R6: packed f32x2 math (PTX fma.rn.f32x2). Each lane's W2/W3
// column is pre-packed (w,w) in 64-bit regs; all activations/tangents carry a
// sample PAIR. Halves FFMA issue count per sample. All state is named scalars.

#define BETAF 20.0f
#define INV_BETAF 0.05f
#define BLOCK 128
#define WPB (BLOCK / 32)
#define GRID 304   // 152 SMs x 2 resident blocks, persistent loop

typedef unsigned long long ull;

__device__ __forceinline__ ull pk2(float lo, float hi) {
    ull d; unsigned l = __float_as_uint(lo), h = __float_as_uint(hi);
    asm("mov.b64 %0, {%1, %2};" : "=l"(d) : "r"(l), "r"(h));
    return d;
}
__device__ __forceinline__ void upk2(ull s, float& lo, float& hi) {
    unsigned l, h;
    asm("mov.b64 {%0, %1}, %2;" : "=r"(l), "=r"(h) : "l"(s));
    lo = __uint_as_float(l); hi = __uint_as_float(h);
}
#define FMA2(d,a,b,c) asm("fma.rn.f32x2 %0, %1, %2, %3;" : "=l"(d) : "l"(a), "l"(b), "l"(c))
#define MUL2(d,a,b)   asm("mul.rn.f32x2 %0, %1, %2;"     : "=l"(d) : "l"(a), "l"(b))
#define ADD2(d,a,b)   asm("add.rn.f32x2 %0, %1, %2;"     : "=l"(d) : "l"(a), "l"(b))

__device__ __forceinline__ void act_hd(float z, float& h, float& d) {
    float y = BETAF * z;
    float e = __expf(-fabsf(y));
    float r = __fdividef(1.0f, 1.0f + e);
    d = (y >= 0.0f) ? r : e * r;                       // sigmoid(20z)
    h = fmaxf(z, 0.0f) + __logf(1.0f + e) * INV_BETAF; // softplus(20z)/20
}
__device__ __forceinline__ float act_d(float z) {
    float y = BETAF * z;
    float e = __expf(-fabsf(y));
    float r = __fdividef(1.0f, 1.0f + e);
    return (y >= 0.0f) ? r : e * r;
}

// load one W column entry, packed (w,w): P##i (ull)
#define LWP(i, P, G) ull P##i; { unsigned r_ = __float_as_uint((G)[(i)*32 + lane]); \
    asm("mov.b64 %0, {%1, %2};" : "=l"(P##i) : "r"(r_), "r"(r_)); }
#define REP32(F, A, B) F(0,A,B)F(1,A,B)F(2,A,B)F(3,A,B)F(4,A,B)F(5,A,B)F(6,A,B)F(7,A,B) \
    F(8,A,B)F(9,A,B)F(10,A,B)F(11,A,B)F(12,A,B)F(13,A,B)F(14,A,B)F(15,A,B) \
    F(16,A,B)F(17,A,B)F(18,A,B)F(19,A,B)F(20,A,B)F(21,A,B)F(22,A,B)F(23,A,B) \
    F(24,A,B)F(25,A,B)F(26,A,B)F(27,A,B)F(28,A,B)F(29,A,B)F(30,A,B)F(31,A,B)

// 16 chunks covering neuron pairs (2i, 2i+1)
#define REPCH(F, P, B) F(P,0,0,1,B)F(P,1,2,3,B)F(P,2,4,5,B)F(P,3,6,7,B) \
    F(P,4,8,9,B)F(P,5,10,11,B)F(P,6,12,13,B)F(P,7,14,15,B) \
    F(P,8,16,17,B)F(P,9,18,19,B)F(P,10,20,21,B)F(P,11,22,23,B) \
    F(P,12,24,25,B)F(P,13,26,27,B)F(P,14,28,29,B)F(P,15,30,31,B)

// forward chunk: one LDS.128 = h-pairs of neurons n0,n1 ; 2 FFMA2
#define FWDC(P, i, n0, n1, HB) { \
    const ulonglong2 hp_ = ((const ulonglong2*)(HB))[i]; \
    FMA2(accA, hp_.x, P##n0, accA); FMA2(accB, hp_.y, P##n1, accB); }

// tangent chunk: 3 LDS.128 (one per tangent j), 6 FFMA2
#define TRIC(P, i, n0, n1, TB) { \
    const ulonglong2 q0_ = ((const ulonglong2*)(TB))[i]; \
    const ulonglong2 q1_ = ((const ulonglong2*)((TB) + 64))[i]; \
    const ulonglong2 q2_ = ((const ulonglong2*)((TB) + 128))[i]; \
    FMA2(a0, q0_.x, P##n0, a0); FMA2(a1, q1_.x, P##n0, a1); FMA2(a2, q2_.x, P##n0, a2); \
    FMA2(a0, q0_.y, P##n1, a0); FMA2(a1, q1_.y, P##n1, a1); FMA2(a2, q2_.y, P##n1, a2); }

__global__ __launch_bounds__(BLOCK, 2) void NCL_50766513438744_kernel(
    const float* __restrict__ x,
    const float* __restrict__ W1, const float* __restrict__ b1,
    const float* __restrict__ W2, const float* __restrict__ b2,
    const float* __restrict__ W3, const float* __restrict__ b3,
    const float* __restrict__ W4,
    float* __restrict__ out, int N, int totalWarps)
{
    // per-warp buffers (floats): hb1[64] hb2[64] tb1[192] tb2[192] = 512
    __shared__ __align__(16) float sBuf[WPB * 512];

    const int lane = threadIdx.x & 31;
    const int wib  = threadIdx.x >> 5;
    float* const hb1 = &sBuf[wib * 512];
    float* const hb2 = hb1 + 64;
    float* const tb1 = hb1 + 128;
    float* const tb2 = hb1 + 320;
    ull* const hb1u = (ull*)hb1;
    ull* const hb2u = (ull*)hb2;
    ull* const tb1u = (ull*)tb1;
    ull* const tb2u = (ull*)tb2;

    // packed W2/W3 columns for this lane (loop-invariant)
    REP32(LWP, w2, W2)
    REP32(LWP, w3, W3)

    const ull w1p0 = pk2(W1[lane], W1[lane]);
    const ull w1p1 = pk2(W1[32 + lane], W1[32 + lane]);
    const ull w1p2 = pk2(W1[64 + lane], W1[64 + lane]);
    const ull b1p  = pk2(b1[lane], b1[lane]);
    const ull b2p  = pk2(b2[lane], b2[lane]);
    const ull b3p  = pk2(b3[lane], b3[lane]);
    const float w4_0 = W4[lane * 3 + 0], w4_1 = W4[lane * 3 + 1], w4_2 = W4[lane * 3 + 2];

    const int pairs = (N + 1) >> 1;
    const int gw = blockIdx.x * WPB + wib;
    for (int p = gw; p < pairs; p += totalWarps) {
        const int iA = 2 * p;
        const int iB = (2 * p + 1 < N) ? 2 * p + 1 : 2 * p;
        const float* xA = x + 3 * iA;
        const float* xB = x + 3 * iB;
        const ull x0p = pk2(__ldg(xA + 0), __ldg(xB + 0));
        const ull x1p = pk2(__ldg(xA + 1), __ldg(xB + 1));
        const ull x2p = pk2(__ldg(xA + 2), __ldg(xB + 2));

        // ---- layer 1 ----
        ull z1 = b1p;
        FMA2(z1, x0p, w1p0, z1);
        FMA2(z1, x1p, w1p1, z1);
        FMA2(z1, x2p, w1p2, z1);
        float zA, zB, hA, hB, dA, dB;
        upk2(z1, zA, zB);
        act_hd(zA, hA, dA); act_hd(zB, hB, dB);
        const ull d1p = pk2(dA, dB);
        hb1u[lane] = pk2(hA, hB);
        __syncwarp();

        // ---- layer 2 forward ----
        ull accA = b2p, accB = 0ull;
        REPCH(FWDC, w2, hb1)
        ADD2(accA, accA, accB);
        upk2(accA, zA, zB);
        act_hd(zA, hA, dA); act_hd(zB, hB, dB);
        const ull d2p = pk2(dA, dB);
        hb2u[lane] = pk2(hA, hB);
        // tangent seeds: t1_j = d1 * W1[j][m]
        ull t;
        MUL2(t, d1p, w1p0); tb1u[lane] = t;
        MUL2(t, d1p, w1p1); tb1u[32 + lane] = t;
        MUL2(t, d1p, w1p2); tb1u[64 + lane] = t;
        __syncwarp();

        // ---- layer 3 forward (derivative only) + tangent layer 2 ----
        accA = b3p; accB = 0ull;
        REPCH(FWDC, w3, hb2)
        ull a0 = 0ull, a1 = 0ull, a2 = 0ull;
        REPCH(TRIC, w2, tb1)
        ADD2(accA, accA, accB);
        upk2(accA, zA, zB);
        const ull d3p = pk2(act_d(zA), act_d(zB));
        MUL2(t, d2p, a0); tb2u[lane] = t;
        MUL2(t, d2p, a1); tb2u[32 + lane] = t;
        MUL2(t, d2p, a2); tb2u[64 + lane] = t;
        __syncwarp();

        // ---- tangent layer 3 ----
        a0 = 0ull; a1 = 0ull; a2 = 0ull;
        REPCH(TRIC, w3, tb2)
        ull s0p, s1p, s2p;
        MUL2(s0p, d3p, a0); MUL2(s1p, d3p, a1); MUL2(s2p, d3p, a2);
        float s0A, s0B, s1A, s1B, s2A, s2B;
        upk2(s0p, s0A, s0B); upk2(s1p, s1A, s1B); upk2(s2p, s2A, s2B);

        // ---- layer 4 + antisymmetric trace contraction (per-lane partials) ----
        const float po0A = fmaf(s1A, w4_0, s2A * w4_1);
        const float po1A = fmaf(s2A, w4_2, -(s0A * w4_0));
        const float po2A = -fmaf(s0A, w4_1, s1A * w4_2);
        const float po0B = fmaf(s1B, w4_0, s2B * w4_1);
        const float po1B = fmaf(s2B, w4_2, -(s0B * w4_0));
        const float po2B = -fmaf(s0B, w4_1, s1B * w4_2);

        ull po0 = pk2(po0A, po0B), po1 = pk2(po1A, po1B), po2 = pk2(po2A, po2B);
        #pragma unroll
        for (int off = 16; off; off >>= 1) {
            ull v0 = __shfl_xor_sync(0xffffffffu, po0, off);
            ull v1 = __shfl_xor_sync(0xffffffffu, po1, off);
            ull v2 = __shfl_xor_sync(0xffffffffu, po2, off);
            ADD2(po0, po0, v0); ADD2(po1, po1, v1); ADD2(po2, po2, v2);
        }
        if (lane == 0) {
            float r0A, r0B, r1A, r1B, r2A, r2B;
            upk2(po0, r0A, r0B); upk2(po1, r1A, r1B); upk2(po2, r2A, r2B);
            out[3 * iA + 0] = r0A; out[3 * iA + 1] = r1A; out[3 * iA + 2] = r2A;
            if (iB != iA) {
                out[3 * iB + 0] = r0B; out[3 * iB + 1] = r1B; out[3 * iB + 2] = r2B;
            }
        }
        // loop-carried smem reuse ordered by the syncwarps above
    }
}

extern "C" void kernel_launch(void* const* d_in, const int* in_sizes, int n_in,
                              void* d_out, int out_size) {
    const float* x  = (const float*)d_in[0];
    const float* W1 = (const float*)d_in[1];
    const float* b1 = (const float*)d_in[2];
    const float* W2 = (const float*)d_in[3];
    const float* b2 = (const float*)d_in[4];
    const float* W3 = (const float*)d_in[5];
    const float* b3 = (const float*)d_in[6];
    const float* W4 = (const float*)d_in[7];
    // d_in[8] = b4: not needed (bias drops out of the Jacobian)
    float* out = (float*)d_out;

    const int N = in_sizes[0] / 3;
    const int totalWarps = GRID * WPB;
    NCL_50766513438744_kernel<<<GRID, BLOCK>>>(x, W1, b1, W2, b2, W3, b3, W4,
                                               out, N, totalWarps);
}

// round 9
// speedup vs baseline: 1.9299x; 1.1463x over previous
#include <cuda_runtime.h>
#include <cuda_bf16.h>

// out[n,:] = trace-contraction of the Jacobian of the antisymmetric field
// A(p)=M-M^T (M upper-tri from v=MLP(p), 3->32->32->32->3, softplus beta=20):
//   out0 =  Jv[0][1] + Jv[1][2]
//   out1 = -Jv[0][0] + Jv[2][2]
//   out2 = -Jv[1][0] - Jv[2][1],   Jv[c][j] = dv_c/dx_j
// Forward (sigmoid(20z) diagonals) + 3 simultaneous forward-mode tangents.
//
// R8 decomposition (cuts broadcast-LDS issue count, the R7 83.8% l1tex wall):
//   half-warp <-> sample, lane <-> column pair (2q, 2q+1).
// Each lane reads ONLY its sample's exchange vector (halves LDS.128 count),
// f32x2 packs the K axis: LDS.128 yields (t[k],t[k+1]) pairs FMA2'd against
// pre-packed weight k-pairs; horizontal add at matvec end. Weights stay in
// registers. All state named scalars (no local-mem pathway).

#define BETAF 20.0f
#define INV_BETAF 0.05f
#define BLOCK 128
#define WPB (BLOCK / 32)
#define GRID 304   // 152 SMs x 2 resident blocks, persistent loop

typedef unsigned long long ull;

__device__ __forceinline__ ull pk2(float lo, float hi) {
    ull d;
    asm("mov.b64 %0, {%1, %2};" : "=l"(d)
        : "r"(__float_as_uint(lo)), "r"(__float_as_uint(hi)));
    return d;
}
__device__ __forceinline__ void upk2(ull s, float& lo, float& hi) {
    unsigned l, h;
    asm("mov.b64 {%0, %1}, %2;" : "=r"(l), "=r"(h) : "l"(s));
    lo = __uint_as_float(l); hi = __uint_as_float(h);
}
__device__ __forceinline__ float hadd2(ull s) {
    float lo, hi; upk2(s, lo, hi); return lo + hi;
}
#define FMA2(d,a,b,c) asm("fma.rn.f32x2 %0, %1, %2, %3;" : "=l"(d) : "l"(a), "l"(b), "l"(c))

__device__ __forceinline__ void act_hd(float z, float& h, float& d) {
    float y = BETAF * z;
    float e = __expf(-fabsf(y));
    float r = __fdividef(1.0f, 1.0f + e);
    d = (y >= 0.0f) ? r : e * r;                       // sigmoid(20z)
    h = fmaxf(z, 0.0f) + __logf(1.0f + e) * INV_BETAF; // softplus(20z)/20
}
__device__ __forceinline__ float act_d(float z) {
    float y = BETAF * z;
    float e = __expf(-fabsf(y));
    float r = __fdividef(1.0f, 1.0f + e);
    return (y >= 0.0f) ? r : e * r;
}

// weight k-pair register: P##i = (G[2i][col], G[2i+1][col])
#define LWK(i, P, G, col) const ull P##i = pk2((G)[(2*(i))*32 + (col)], (G)[(2*(i)+1)*32 + (col)]);
#define REP16(F, P, G, C) F(0,P,G,C)F(1,P,G,C)F(2,P,G,C)F(3,P,G,C)F(4,P,G,C)F(5,P,G,C)F(6,P,G,C)F(7,P,G,C) \
    F(8,P,G,C)F(9,P,G,C)F(10,P,G,C)F(11,P,G,C)F(12,P,G,C)F(13,P,G,C)F(14,P,G,C)F(15,P,G,C)

// forward chunk i: one LDS.128 = k-values 4i..4i+3 of THIS lane's sample
#define FWDC(PE, PO, i, j0, j1, B) { \
    const ulonglong2 v = reinterpret_cast<const ulonglong2*>(B)[i]; \
    FMA2(fE, v.x, PE##j0, fE); FMA2(fE, v.y, PE##j1, fE); \
    FMA2(fO, v.x, PO##j0, fO); FMA2(fO, v.y, PO##j1, fO); }
#define FWD_ALL(PE, PO, B) \
    FWDC(PE,PO,0,0,1,B) FWDC(PE,PO,1,2,3,B) FWDC(PE,PO,2,4,5,B) FWDC(PE,PO,3,6,7,B) \
    FWDC(PE,PO,4,8,9,B) FWDC(PE,PO,5,10,11,B) FWDC(PE,PO,6,12,13,B) FWDC(PE,PO,7,14,15,B)

// tangent chunk i: 3 LDS.128 (one per tangent j), 12 FMA2
#define TRIC(PE, PO, i, j0, j1, T) { \
    const ulonglong2 v0 = reinterpret_cast<const ulonglong2*>(T)[i]; \
    const ulonglong2 v1 = reinterpret_cast<const ulonglong2*>((T)+32)[i]; \
    const ulonglong2 v2 = reinterpret_cast<const ulonglong2*>((T)+64)[i]; \
    FMA2(t0E, v0.x, PE##j0, t0E); FMA2(t0E, v0.y, PE##j1, t0E); \
    FMA2(t0O, v0.x, PO##j0, t0O); FMA2(t0O, v0.y, PO##j1, t0O); \
    FMA2(t1E, v1.x, PE##j0, t1E); FMA2(t1E, v1.y, PE##j1, t1E); \
    FMA2(t1O, v1.x, PO##j0, t1O); FMA2(t1O, v1.y, PO##j1, t1O); \
    FMA2(t2E, v2.x, PE##j0, t2E); FMA2(t2E, v2.y, PE##j1, t2E); \
    FMA2(t2O, v2.x, PO##j0, t2O); FMA2(t2O, v2.y, PO##j1, t2O); }
#define TRI_ALL(PE, PO, T) \
    TRIC(PE,PO,0,0,1,T) TRIC(PE,PO,1,2,3,T) TRIC(PE,PO,2,4,5,T) TRIC(PE,PO,3,6,7,T) \
    TRIC(PE,PO,4,8,9,T) TRIC(PE,PO,5,10,11,T) TRIC(PE,PO,6,12,13,T) TRIC(PE,PO,7,14,15,T)

// smem layout per warp (floats); sample-B bases offset 16B to split bank groups
#define HB_S 36
#define TB_S 100
#define OFF_HB1 0
#define OFF_HB2 72
#define OFF_TB1 144
#define OFF_TB2 344
#define WARP_FLOATS 544

__global__ __launch_bounds__(BLOCK, 2) void NCL_50766513438744_kernel(
    const float* __restrict__ x,
    const float* __restrict__ W1, const float* __restrict__ b1,
    const float* __restrict__ W2, const float* __restrict__ b2,
    const float* __restrict__ W3, const float* __restrict__ b3,
    const float* __restrict__ W4,
    float* __restrict__ out, int N, int totalWarps)
{
    __shared__ __align__(16) float sBuf[WPB * WARP_FLOATS];

    const int lane = threadIdx.x & 31;
    const int wib  = threadIdx.x >> 5;
    const int smp  = lane >> 4;        // 0 = sample A, 1 = sample B
    const int q    = lane & 15;
    const int colE = 2 * q;
    const int colO = 2 * q + 1;

    float* const wbase = &sBuf[wib * WARP_FLOATS];
    float* const hb1s = wbase + OFF_HB1 + smp * HB_S;   // this sample's h1[32]
    float* const hb2s = wbase + OFF_HB2 + smp * HB_S;
    float* const tb1s = wbase + OFF_TB1 + smp * TB_S;   // t1[3][32]
    float* const tb2s = wbase + OFF_TB2 + smp * TB_S;

    // loop-invariant weights (k-pair packed, per column)
    REP16(LWK, w2e, W2, colE)
    REP16(LWK, w2o, W2, colO)
    REP16(LWK, w3e, W3, colE)
    REP16(LWK, w3o, W3, colO)

    const float w1e0 = W1[colE], w1e1 = W1[32 + colE], w1e2 = W1[64 + colE];
    const float w1o0 = W1[colO], w1o1 = W1[32 + colO], w1o2 = W1[64 + colO];
    const float b1E = b1[colE], b1O = b1[colO];
    const float b2E = b2[colE], b2O = b2[colO];
    const float b3E = b3[colE], b3O = b3[colO];
    const float w4e0 = W4[colE*3+0], w4e1 = W4[colE*3+1], w4e2 = W4[colE*3+2];
    const float w4o0 = W4[colO*3+0], w4o1 = W4[colO*3+1], w4o2 = W4[colO*3+2];

    const int pairs = (N + 1) >> 1;
    const int gw = blockIdx.x * WPB + wib;
    for (int p = gw; p < pairs; p += totalWarps) {
        const int iA = 2 * p;
        const int iB = (2 * p + 1 < N) ? 2 * p + 1 : 2 * p;
        const int myIdx = smp ? iB : iA;
        const float x0 = __ldg(x + 3 * myIdx + 0);
        const float x1 = __ldg(x + 3 * myIdx + 1);
        const float x2 = __ldg(x + 3 * myIdx + 2);

        // ===== phase A: layer 1 + tangent seeds (columns colE, colO) =====
        float hE, dE, hO, dO;
        act_hd(fmaf(x0, w1e0, fmaf(x1, w1e1, fmaf(x2, w1e2, b1E))), hE, dE);
        act_hd(fmaf(x0, w1o0, fmaf(x1, w1o1, fmaf(x2, w1o2, b1O))), hO, dO);
        reinterpret_cast<ull*>(hb1s)[q] = pk2(hE, hO);
        reinterpret_cast<ull*>(tb1s     )[q] = pk2(dE * w1e0, dO * w1o0);
        reinterpret_cast<ull*>(tb1s + 32)[q] = pk2(dE * w1e1, dO * w1o1);
        reinterpret_cast<ull*>(tb1s + 64)[q] = pk2(dE * w1e2, dO * w1o2);
        const float d1E = dE, d1O = dO;   // kept only for nothing further; seeds done
        (void)d1E; (void)d1O;
        __syncwarp();

        // ===== phase B: layer-2 forward + tangent layer 2 =====
        ull fE = pk2(b2E, 0.0f), fO = pk2(b2O, 0.0f);
        FWD_ALL(w2e, w2o, hb1s)
        ull t0E = 0ull, t0O = 0ull, t1E = 0ull, t1O = 0ull, t2E = 0ull, t2O = 0ull;
        TRI_ALL(w2e, w2o, tb1s)
        float h2E, d2E, h2O, d2O;
        act_hd(hadd2(fE), h2E, d2E);
        act_hd(hadd2(fO), h2O, d2O);
        reinterpret_cast<ull*>(hb2s)[q] = pk2(h2E, h2O);
        reinterpret_cast<ull*>(tb2s     )[q] = pk2(d2E * hadd2(t0E), d2O * hadd2(t0O));
        reinterpret_cast<ull*>(tb2s + 32)[q] = pk2(d2E * hadd2(t1E), d2O * hadd2(t1O));
        reinterpret_cast<ull*>(tb2s + 64)[q] = pk2(d2E * hadd2(t2E), d2O * hadd2(t2O));
        __syncwarp();

        // ===== phase C: layer-3 forward (deriv only) + tangent layer 3 =====
        fE = pk2(b3E, 0.0f); fO = pk2(b3O, 0.0f);
        FWD_ALL(w3e, w3o, hb2s)
        t0E = 0ull; t0O = 0ull; t1E = 0ull; t1O = 0ull; t2E = 0ull; t2O = 0ull;
        TRI_ALL(w3e, w3o, tb2s)
        const float d3E = act_d(hadd2(fE));
        const float d3O = act_d(hadd2(fO));
        const float s0E = d3E * hadd2(t0E), s0O = d3O * hadd2(t0O);
        const float s1E = d3E * hadd2(t1E), s1O = d3O * hadd2(t1O);
        const float s2E = d3E * hadd2(t2E), s2O = d3O * hadd2(t2O);

        // layer 4 + antisymmetric trace contraction (this lane's 2 columns)
        float po0 = fmaf(s1E, w4e0, fmaf(s2E, w4e1, fmaf(s1O, w4o0, s2O * w4o1)));
        float po1 = fmaf(s2E, w4e2, fmaf(-s0E, w4e0, fmaf(s2O, w4o2, -(s0O * w4o0))));
        float po2 = -fmaf(s0E, w4e1, fmaf(s1E, w4e2, fmaf(s0O, w4o1, s1O * w4o2)));

        // half-warp reduction (16 lanes of this sample)
        #pragma unroll
        for (int off = 8; off; off >>= 1) {
            po0 += __shfl_xor_sync(0xffffffffu, po0, off);
            po1 += __shfl_xor_sync(0xffffffffu, po1, off);
            po2 += __shfl_xor_sync(0xffffffffu, po2, off);
        }
        if (q == 0 && (smp == 0 || iB != iA)) {
            out[3 * myIdx + 0] = po0;
            out[3 * myIdx + 1] = po1;
            out[3 * myIdx + 2] = po2;
        }
        // next-iter phase-A stores (hb1/tb1) are separated from this iter's
        // phase-C reads (hb2/tb2) by the phase-A syncwarp; no extra sync needed
    }
}

extern "C" void kernel_launch(void* const* d_in, const int* in_sizes, int n_in,
                              void* d_out, int out_size) {
    const float* x  = (const float*)d_in[0];
    const float* W1 = (const float*)d_in[1];
    const float* b1 = (const float*)d_in[2];
    const float* W2 = (const float*)d_in[3];
    const float* b2 = (const float*)d_in[4];
    const float* W3 = (const float*)d_in[5];
    const float* b3 = (const float*)d_in[6];
    const float* W4 = (const float*)d_in[7];
    // d_in[8] = b4: not needed (bias drops out of the Jacobian)
    float* out = (float*)d_out;

    const int N = in_sizes[0] / 3;
    const int totalWarps = GRID * WPB;
    NCL_50766513438744_kernel<<<GRID, BLOCK>>>(x, W1, b1, W2, b2, W3, b3, W4,
                                               out, N, totalWarps);
}